// round 12
// baseline (speedup 1.0000x reference)
#include <cuda_runtime.h>
#include <cuda_fp16.h>
#include <cstdint>
#include <math.h>

#define DI __device__ __forceinline__

// ---------------- problem constants ----------------
constexpr int T     = 441000;
constexpr int L     = 44100;
constexpr int BATCH = 32;
constexpr int NFFT  = 8192;
constexpr int HOP   = 4096;
constexpr int NBLK  = 108;              // ceil(T / HOP)
constexpr int NP    = 11;               // ceil(L / HOP) IR partitions
constexpr int NPAIR = BATCH / 2;        // 16 complex-packed row pairs
constexpr int NTH   = 512;              // threads per FFT CTA (16 warps)

constexpr int SMEMB = NFFT * 8;         // 65536 B: single buffer (in-place FFT)

// ---------------- global scratch ----------------
__device__ __align__(128) __half2 g_spec[(size_t)NPAIR * NBLK * NFFT];  // 54 MB (half2 spectra)
__device__ __align__(128) float2  g_H[(size_t)NP * NFFT];               // 704 KB fp32 (prescaled 1/N)
__device__ float2 g_tw[NFFT];                                           // e^{-2pi i t / NFFT}

// pair-granular swizzle: pair = 2 complexes = 16B. Conflict-free for all patterns used.
DI int SWP(int q) { return q ^ ((q >> 3) & 7); }
// complex-index view (consistent with pair layout)
DI int SWZ(int a) { return (SWP(a >> 1) << 1) | (a & 1); }

// ---------------- register DFTs (sign sg=+1 fwd e^{-}, sg=-1 inv e^{+}) ----
DI void dft8(float* xr, float* xi, float sg) {
    const float c = 0.70710678118654752f;
    float t0r = xr[0] + xr[4], t0i = xi[0] + xi[4];
    float t1r = xr[0] - xr[4], t1i = xi[0] - xi[4];
    float t2r = xr[2] + xr[6], t2i = xi[2] + xi[6];
    float t3r = xr[2] - xr[6], t3i = xi[2] - xi[6];
    float w3r = sg * t3i, w3i = -sg * t3r;              // W4 * t3
    float E0r = t0r + t2r, E0i = t0i + t2i;
    float E1r = t1r + w3r, E1i = t1i + w3i;
    float E2r = t0r - t2r, E2i = t0i - t2i;
    float E3r = t1r - w3r, E3i = t1i - w3i;
    float u0r = xr[1] + xr[5], u0i = xi[1] + xi[5];
    float u1r = xr[1] - xr[5], u1i = xi[1] - xi[5];
    float u2r = xr[3] + xr[7], u2i = xi[3] + xi[7];
    float u3r = xr[3] - xr[7], u3i = xi[3] - xi[7];
    float v3r = sg * u3i, v3i = -sg * u3r;
    float O0r = u0r + u2r, O0i = u0i + u2i;
    float O1r = u1r + v3r, O1i = u1i + v3i;
    float O2r = u0r - u2r, O2i = u0i - u2i;
    float O3r = u1r - v3r, O3i = u1i - v3i;
    xr[0] = E0r + O0r; xi[0] = E0i + O0i;
    xr[4] = E0r - O0r; xi[4] = E0i - O0i;
    float p1r = c * (O1r + sg * O1i), p1i = c * (O1i - sg * O1r);   // W8^1 * O1
    xr[1] = E1r + p1r; xi[1] = E1i + p1i;
    xr[5] = E1r - p1r; xi[5] = E1i - p1i;
    float p2r = sg * O2i, p2i = -sg * O2r;                          // W8^2 * O2
    xr[2] = E2r + p2r; xi[2] = E2i + p2i;
    xr[6] = E2r - p2r; xi[6] = E2i - p2i;
    float p3r = c * (sg * O3i - O3r), p3i = -c * (O3i + sg * O3r);  // W8^3 * O3
    xr[3] = E3r + p3r; xi[3] = E3i + p3i;
    xr[7] = E3r - p3r; xi[7] = E3i - p3i;
}

DI void dft16(float* xr, float* xi, float sg) {
    const float C16[8] = {1.f, 0.92387953251128674f, 0.70710678118654752f, 0.38268343236508977f,
                          0.f, -0.38268343236508977f, -0.70710678118654752f, -0.92387953251128674f};
    const float S16[8] = {0.f, 0.38268343236508977f, 0.70710678118654752f, 0.92387953251128674f,
                          1.f, 0.92387953251128674f, 0.70710678118654752f, 0.38268343236508977f};
    float er[8], ei[8], orr[8], oii[8];
    #pragma unroll
    for (int j = 0; j < 8; j++) {
        er[j] = xr[2 * j];     ei[j] = xi[2 * j];
        orr[j] = xr[2 * j + 1]; oii[j] = xi[2 * j + 1];
    }
    dft8(er, ei, sg);
    dft8(orr, oii, sg);
    #pragma unroll
    for (int k = 0; k < 8; k++) {
        float wr = C16[k], wi = -S16[k] * sg;
        float pr = wr * orr[k] - wi * oii[k];
        float pi = wr * oii[k] + wi * orr[k];
        xr[k]     = er[k] + pr; xi[k]     = ei[k] + pi;
        xr[k + 8] = er[k] - pr; xi[k + 8] = ei[k] - pi;
    }
}

// ---------------- pair-vectorized in-place Stockham radix-8 stage --------
// Thread handles adjacent groups g0=2*tid, g0+1. Reads/writes are LDS.128/STS.128.
// SS in {1, 8, 64}; twiddle step == SS.
template <int SS>
DI void stage8v(float4* sv, float sg) {
    const int tid = threadIdx.x;
    float ar0[8], ai0[8], ar1[8], ai1[8];
    #pragma unroll
    for (int j = 0; j < 8; j++) {
        float4 v = sv[SWP(tid + 512 * j)];
        ar0[j] = v.x; ai0[j] = v.y; ar1[j] = v.z; ai1[j] = v.w;
    }
    __syncthreads();
    dft8(ar0, ai0, sg);
    dft8(ar1, ai1, sg);
    if (SS == 1) {
        const int g0 = 2 * tid;
        // group0 -> pairs 8*tid + 0..3 (k = 2m, 2m+1); twiddle idx g0*k
        sv[SWP(8 * tid)] = make_float4(
            ar0[0], ai0[0],
            ar0[1] * g_tw[g0 & 8191].x - ai0[1] * (g_tw[g0 & 8191].y * sg),
            ar0[1] * (g_tw[g0 & 8191].y * sg) + ai0[1] * g_tw[g0 & 8191].x);
        #pragma unroll
        for (int m = 1; m < 4; m++) {
            int k0 = 2 * m, k1 = 2 * m + 1;
            float2 wa = g_tw[(g0 * k0) & 8191];
            float2 wb = g_tw[(g0 * k1) & 8191];
            float wai = wa.y * sg, wbi = wb.y * sg;
            sv[SWP(8 * tid + m)] = make_float4(
                ar0[k0] * wa.x - ai0[k0] * wai, ar0[k0] * wai + ai0[k0] * wa.x,
                ar0[k1] * wb.x - ai0[k1] * wbi, ar0[k1] * wbi + ai0[k1] * wb.x);
        }
        // group1 -> pairs 8*tid + 4..7; twiddle idx (g0+1)*k
        sv[SWP(8 * tid + 4)] = make_float4(
            ar1[0], ai1[0],
            ar1[1] * g_tw[(g0 + 1) & 8191].x - ai1[1] * (g_tw[(g0 + 1) & 8191].y * sg),
            ar1[1] * (g_tw[(g0 + 1) & 8191].y * sg) + ai1[1] * g_tw[(g0 + 1) & 8191].x);
        #pragma unroll
        for (int m = 1; m < 4; m++) {
            int k0 = 2 * m, k1 = 2 * m + 1;
            float2 wa = g_tw[((g0 + 1) * k0) & 8191];
            float2 wb = g_tw[((g0 + 1) * k1) & 8191];
            float wai = wa.y * sg, wbi = wb.y * sg;
            sv[SWP(8 * tid + 4 + m)] = make_float4(
                ar1[k0] * wa.x - ai1[k0] * wai, ar1[k0] * wai + ai1[k0] * wa.x,
                ar1[k1] * wb.x - ai1[k1] * wbi, ar1[k1] * wbi + ai1[k1] * wb.x);
        }
    } else {
        // both groups share p -> shared twiddle per k
        const int p  = (SS == 8) ? (tid >> 2) : (tid >> 5);
        const int pb = (SS == 8) ? ((tid & 3) + 32 * (tid >> 2))
                                 : ((tid & 31) + 256 * (tid >> 5));
        constexpr int KS = SS / 2;          // pair stride per k
        sv[SWP(pb)] = make_float4(ar0[0], ai0[0], ar1[0], ai1[0]);
        #pragma unroll
        for (int k = 1; k < 8; k++) {
            float2 w = g_tw[(SS * p * k) & 8191];
            float wi = w.y * sg;
            sv[SWP(pb + KS * k)] = make_float4(
                ar0[k] * w.x - ai0[k] * wi, ar0[k] * wi + ai0[k] * w.x,
                ar1[k] * w.x - ai1[k] * wi, ar1[k] * wi + ai1[k] * w.x);
        }
    }
    __syncthreads();
}

DI void stage16_ip(float2* s, float sg) {
    float ar[16], ai[16];
    const int g = threadIdx.x;
    #pragma unroll
    for (int j = 0; j < 16; j++) {
        float2 v = s[SWZ(g + 512 * j)];
        ar[j] = v.x; ai[j] = v.y;
    }
    __syncthreads();
    dft16(ar, ai, sg);
    #pragma unroll
    for (int k = 0; k < 16; k++)
        s[SWZ(g + 512 * k)] = make_float2(ar[k], ai[k]);
    __syncthreads();
}

// full 8192-pt complex FFT in-place over swizzled smem; natural order result.
DI void fft8192_ip(float4* sv, float sg) {
    stage8v<1>(sv, sg);
    stage8v<8>(sv, sg);
    stage8v<64>(sv, sg);
    stage16_ip((float2*)sv, sg);
}

// ---------------- kernels ----------------
__global__ void __launch_bounds__(256) twiddle_kernel() {
    int t = blockIdx.x * 256 + threadIdx.x;
    double s, c;
    sincos(2.0 * 3.14159265358979323846 * (double)t / (double)NFFT, &s, &c);
    g_tw[t] = make_float2((float)c, (float)(-s));
}

// fwd_kernel: blocks [0, NPAIR*NBLK) do x spectra; blocks [NPAIR*NBLK, +NP) do IR partitions
__global__ void __launch_bounds__(NTH, 2) fwd_kernel(const float* __restrict__ x,
                                                     const float* __restrict__ ir) {
    extern __shared__ float4 sv[];
    float2* s2 = (float2*)sv;
    const int b = blockIdx.x;
    const int tid = threadIdx.x;

    if (b < NPAIR * NBLK) {
        const int pair = b / NBLK;
        const int t = b - pair * NBLK;
        const float* x0 = x + (size_t)(2 * pair) * T;
        const float* x1 = x + (size_t)(2 * pair + 1) * T;
        const int off = (t - 1) * HOP;      // multiple of 4096 (possibly negative)
        #pragma unroll
        for (int i = 0; i < 4; i++) {
            int u = tid + NTH * i;
            int n = off + 4 * u;
            float4 v0 = make_float4(0.f, 0.f, 0.f, 0.f), v1 = v0;
            if (n >= 0 && n < T) {          // vector-aligned: n%4==0, T%4==0
                v0 = *(const float4*)(x0 + n);
                v1 = *(const float4*)(x1 + n);
            }
            sv[SWP(2 * u)]     = make_float4(v0.x, v1.x, v0.y, v1.y);
            sv[SWP(2 * u + 1)] = make_float4(v0.z, v1.z, v0.w, v1.w);
        }
        __syncthreads();
        fft8192_ip(sv, 1.f);
        uint4* dst = (uint4*)(g_spec + (size_t)b * NFFT);
        #pragma unroll
        for (int i = 0; i < 4; i++) {
            int k4 = tid + NTH * i;
            float4 a = sv[SWP(2 * k4)];      // complexes 4k4, 4k4+1
            float4 c = sv[SWP(2 * k4 + 1)];  // complexes 4k4+2, 4k4+3
            uint4 o;
            *(__half2*)&o.x = __floats2half2_rn(a.x, a.y);
            *(__half2*)&o.y = __floats2half2_rn(a.z, a.w);
            *(__half2*)&o.z = __floats2half2_rn(c.x, c.y);
            *(__half2*)&o.w = __floats2half2_rn(c.z, c.w);
            dst[k4] = o;
        }
    } else {
        const int p = b - NPAIR * NBLK;
        for (int j = tid; j < NFFT; j += NTH) {
            int idx = p * HOP + j;
            float v = (j < HOP && idx < L) ? ir[idx] : 0.f;
            s2[SWZ(j)] = make_float2(v, 0.f);
        }
        __syncthreads();
        fft8192_ip(sv, 1.f);
        const float inv = 1.f / (float)NFFT;
        float2* dst = g_H + (size_t)p * NFFT;
        for (int k = tid; k < NFFT; k += NTH) {
            float2 v = s2[SWZ(k)];
            dst[k] = make_float2(v.x * inv, v.y * inv);
        }
    }
}

// complex MAC: 4 half2 X complexes (uint4) times 4 fp32 H complexes (2 x float4)
DI void cmac4(float4& a01, float4& a23, const uint4& xv,
              const float4& h01, const float4& h23) {
    const __half2* xh = (const __half2*)&xv;
    float2 x0 = __half22float2(xh[0]);
    float2 x1 = __half22float2(xh[1]);
    float2 x2 = __half22float2(xh[2]);
    float2 x3 = __half22float2(xh[3]);
    a01.x += x0.x * h01.x - x0.y * h01.y;
    a01.y += x0.x * h01.y + x0.y * h01.x;
    a01.z += x1.x * h01.z - x1.y * h01.w;
    a01.w += x1.x * h01.w + x1.y * h01.z;
    a23.x += x2.x * h23.x - x2.y * h23.y;
    a23.y += x2.x * h23.y + x2.y * h23.x;
    a23.z += x3.x * h23.z - x3.y * h23.w;
    a23.w += x3.x * h23.w + x3.y * h23.z;
}

__global__ void __launch_bounds__(NTH, 2) out_kernel(const float* __restrict__ x,
                                                     const float* __restrict__ wetp,
                                                     float* __restrict__ out) {
    extern __shared__ float4 sv[];
    const int b = blockIdx.x;
    const int pair = b / NBLK;
    const int t = b - pair * NBLK;
    const int tid = threadIdx.x;

    // ---- accumulate acc[k] = sum_p X[t-p][k] * H[p][k] ----
    float4 acc[8];
    #pragma unroll
    for (int i = 0; i < 8; i++) acc[i] = make_float4(0.f, 0.f, 0.f, 0.f);

    const uint4* Xbase = (const uint4*)(g_spec + (size_t)(pair * NBLK + t) * NFFT);

    if (t >= NP - 1) {
        #pragma unroll
        for (int p = 0; p < NP; p++) {
            const uint4* X4 = Xbase - (size_t)p * (NFFT / 4);
            const float4* H4 = (const float4*)(g_H + (size_t)p * NFFT);
            #pragma unroll
            for (int i = 0; i < 4; i++) {
                int f = tid + NTH * i;          // quad index: 4 complexes each
                uint4 xv = X4[f];
                float4 h01 = H4[2 * f];
                float4 h23 = H4[2 * f + 1];
                cmac4(acc[2 * i], acc[2 * i + 1], xv, h01, h23);
            }
        }
    } else {
        for (int p = 0; p <= t; p++) {
            const uint4* X4 = Xbase - (size_t)p * (NFFT / 4);
            const float4* H4 = (const float4*)(g_H + (size_t)p * NFFT);
            #pragma unroll
            for (int i = 0; i < 4; i++) {
                int f = tid + NTH * i;
                uint4 xv = X4[f];
                float4 h01 = H4[2 * f];
                float4 h23 = H4[2 * f + 1];
                cmac4(acc[2 * i], acc[2 * i + 1], xv, h01, h23);
            }
        }
    }
    #pragma unroll
    for (int i = 0; i < 4; i++) {
        int u = tid + NTH * i;                  // quad u covers complexes 4u..4u+3
        sv[SWP(2 * u)]     = acc[2 * i];        // (re,im, re,im) of complexes 4u, 4u+1
        sv[SWP(2 * u + 1)] = acc[2 * i + 1];
    }
    __syncthreads();

    // ---- unnormalized inverse FFT (H prescaled by 1/N) ----
    fft8192_ip(sv, -1.f);

    // ---- fused wet/dry store: valid samples are second half j in [HOP, NFFT) ----
    const float wet = 1.f / (1.f + __expf(-wetp[0]));
    const float dry = 1.f - wet;
    const float* x0 = x + (size_t)(2 * pair) * T;
    const float* x1 = x + (size_t)(2 * pair + 1) * T;
    float* o0 = out + (size_t)(2 * pair) * T;
    float* o1 = out + (size_t)(2 * pair + 1) * T;
    #pragma unroll
    for (int i = 0; i < 2; i++) {
        int u = 4 * (tid + NTH * i);
        int n = t * HOP + u;
        if (n < T) {                         // n%4==0, T%4==0 -> whole vector valid
            float4 a = sv[SWP(2048 + u / 2)];       // complexes HOP+u, HOP+u+1
            float4 c = sv[SWP(2048 + u / 2 + 1)];   // complexes HOP+u+2, HOP+u+3
            float4 v0 = *(const float4*)(x0 + n);
            float4 v1 = *(const float4*)(x1 + n);
            float4 r0 = make_float4(dry * v0.x + wet * a.x, dry * v0.y + wet * a.z,
                                    dry * v0.z + wet * c.x, dry * v0.w + wet * c.z);
            float4 r1 = make_float4(dry * v1.x + wet * a.y, dry * v1.y + wet * a.w,
                                    dry * v1.z + wet * c.y, dry * v1.w + wet * c.w);
            *(float4*)(o0 + n) = r0;
            *(float4*)(o1 + n) = r1;
        }
    }
}

// ---------------- launch ----------------
extern "C" void kernel_launch(void* const* d_in, const int* in_sizes, int n_in,
                              void* d_out, int out_size) {
    const float* x    = (const float*)d_in[0];
    const float* ir   = (const float*)d_in[1];
    const float* wetp = (const float*)d_in[2];
    float* out        = (float*)d_out;

    cudaFuncSetAttribute(fwd_kernel, cudaFuncAttributeMaxDynamicSharedMemorySize, SMEMB);
    cudaFuncSetAttribute(out_kernel, cudaFuncAttributeMaxDynamicSharedMemorySize, SMEMB);

    twiddle_kernel<<<NFFT / 256, 256>>>();
    fwd_kernel<<<NPAIR * NBLK + NP, NTH, SMEMB>>>(x, ir);
    out_kernel<<<NPAIR * NBLK, NTH, SMEMB>>>(x, wetp, out);
}

// round 13
// speedup vs baseline: 1.7375x; 1.7375x over previous
#include <cuda_runtime.h>
#include <cuda_fp16.h>
#include <cstdint>
#include <math.h>

#define DI __device__ __forceinline__

// ---------------- problem constants ----------------
constexpr int T     = 441000;
constexpr int L     = 44100;
constexpr int BATCH = 32;
constexpr int NFFT  = 8192;
constexpr int HOP   = 4096;
constexpr int NBLK  = 108;              // ceil(T / HOP)
constexpr int NP    = 11;               // ceil(L / HOP) IR partitions
constexpr int NPAIR = BATCH / 2;        // 16 complex-packed row pairs
constexpr int NTH   = 512;              // threads per FFT CTA (16 warps)

constexpr int SMEMB = NFFT * 8;         // 65536 B: single float2 buffer (in-place FFT)

// ---------------- global scratch ----------------
__device__ __align__(128) __half2 g_spec[(size_t)NPAIR * NBLK * NFFT];  // 54 MB (half2 spectra)
__device__ __align__(128) float2  g_H[(size_t)NP * NFFT];               // 704 KB fp32 (prescaled 1/N)
__device__ float2 g_tw[NFFT];                                           // e^{-2pi i t / NFFT}

// swizzle on float2 index: kills write bank conflicts, preserves read patterns
DI int SWZ(int a) { return a ^ ((a >> 4) & 15); }

// ---------------- register DFTs (sign sg=+1 fwd e^{-}, sg=-1 inv e^{+}) ----
DI void dft8(float* xr, float* xi, float sg) {
    const float c = 0.70710678118654752f;
    float t0r = xr[0] + xr[4], t0i = xi[0] + xi[4];
    float t1r = xr[0] - xr[4], t1i = xi[0] - xi[4];
    float t2r = xr[2] + xr[6], t2i = xi[2] + xi[6];
    float t3r = xr[2] - xr[6], t3i = xi[2] - xi[6];
    float w3r = sg * t3i, w3i = -sg * t3r;              // W4 * t3
    float E0r = t0r + t2r, E0i = t0i + t2i;
    float E1r = t1r + w3r, E1i = t1i + w3i;
    float E2r = t0r - t2r, E2i = t0i - t2i;
    float E3r = t1r - w3r, E3i = t1i - w3i;
    float u0r = xr[1] + xr[5], u0i = xi[1] + xi[5];
    float u1r = xr[1] - xr[5], u1i = xi[1] - xi[5];
    float u2r = xr[3] + xr[7], u2i = xi[3] + xi[7];
    float u3r = xr[3] - xr[7], u3i = xi[3] - xi[7];
    float v3r = sg * u3i, v3i = -sg * u3r;
    float O0r = u0r + u2r, O0i = u0i + u2i;
    float O1r = u1r + v3r, O1i = u1i + v3i;
    float O2r = u0r - u2r, O2i = u0i - u2i;
    float O3r = u1r - v3r, O3i = u1i - v3i;
    xr[0] = E0r + O0r; xi[0] = E0i + O0i;
    xr[4] = E0r - O0r; xi[4] = E0i - O0i;
    float p1r = c * (O1r + sg * O1i), p1i = c * (O1i - sg * O1r);   // W8^1 * O1
    xr[1] = E1r + p1r; xi[1] = E1i + p1i;
    xr[5] = E1r - p1r; xi[5] = E1i - p1i;
    float p2r = sg * O2i, p2i = -sg * O2r;                          // W8^2 * O2
    xr[2] = E2r + p2r; xi[2] = E2i + p2i;
    xr[6] = E2r - p2r; xi[6] = E2i - p2i;
    float p3r = c * (sg * O3i - O3r), p3i = -c * (O3i + sg * O3r);  // W8^3 * O3
    xr[3] = E3r + p3r; xi[3] = E3i + p3i;
    xr[7] = E3r - p3r; xi[7] = E3i - p3i;
}

DI void dft16(float* xr, float* xi, float sg) {
    const float C16[8] = {1.f, 0.92387953251128674f, 0.70710678118654752f, 0.38268343236508977f,
                          0.f, -0.38268343236508977f, -0.70710678118654752f, -0.92387953251128674f};
    const float S16[8] = {0.f, 0.38268343236508977f, 0.70710678118654752f, 0.92387953251128674f,
                          1.f, 0.92387953251128674f, 0.70710678118654752f, 0.38268343236508977f};
    float er[8], ei[8], orr[8], oii[8];
    #pragma unroll
    for (int j = 0; j < 8; j++) {
        er[j] = xr[2 * j];     ei[j] = xi[2 * j];
        orr[j] = xr[2 * j + 1]; oii[j] = xi[2 * j + 1];
    }
    dft8(er, ei, sg);
    dft8(orr, oii, sg);
    #pragma unroll
    for (int k = 0; k < 8; k++) {
        float wr = C16[k], wi = -S16[k] * sg;
        float pr = wr * orr[k] - wi * oii[k];
        float pi = wr * oii[k] + wi * orr[k];
        xr[k]     = er[k] + pr; xi[k]     = ei[k] + pi;
        xr[k + 8] = er[k] - pr; xi[k + 8] = ei[k] - pi;
    }
}

// ---------------- in-place Stockham stages (single float2 buffer) --------
template <int SS, int STEP>
DI void stage8_ip(float2* s, float sg) {
    float ar[2][8], ai[2][8];
    const int g0 = threadIdx.x;
    #pragma unroll
    for (int h = 0; h < 2; h++) {
        const int g = g0 + 512 * h;
        #pragma unroll
        for (int j = 0; j < 8; j++) {
            float2 v = s[SWZ(g + 1024 * j)];
            ar[h][j] = v.x; ai[h][j] = v.y;
        }
    }
    __syncthreads();
    #pragma unroll
    for (int h = 0; h < 2; h++) {
        const int g = g0 + 512 * h;
        const int p = g / SS;
        const int q = g - p * SS;
        dft8(ar[h], ai[h], sg);
        const int ob = q + SS * 8 * p;
        // k = 0: twiddle is exactly (1, 0) -> direct store
        s[SWZ(ob)] = make_float2(ar[h][0], ai[h][0]);
        #pragma unroll
        for (int k = 1; k < 8; k++) {
            int tix = (STEP * p * k) & (NFFT - 1);
            float2 w = g_tw[tix];
            float wi = w.y * sg;
            s[SWZ(ob + SS * k)] = make_float2(ar[h][k] * w.x - ai[h][k] * wi,
                                              ar[h][k] * wi + ai[h][k] * w.x);
        }
    }
    __syncthreads();
}

DI void stage16_ip(float2* s, float sg) {
    float ar[16], ai[16];
    const int g = threadIdx.x;
    #pragma unroll
    for (int j = 0; j < 16; j++) {
        float2 v = s[SWZ(g + 512 * j)];
        ar[j] = v.x; ai[j] = v.y;
    }
    __syncthreads();
    dft16(ar, ai, sg);
    #pragma unroll
    for (int k = 0; k < 16; k++)
        s[SWZ(g + 512 * k)] = make_float2(ar[k], ai[k]);
    __syncthreads();
}

// full 8192-pt complex FFT in-place over swizzled smem; natural order result.
DI void fft8192_ip(float2* s, float sg) {
    stage8_ip<1, 1>(s, sg);
    stage8_ip<8, 8>(s, sg);
    stage8_ip<64, 64>(s, sg);
    stage16_ip(s, sg);
}

// ---------------- kernels ----------------
__global__ void __launch_bounds__(256) twiddle_kernel() {
    int t = blockIdx.x * 256 + threadIdx.x;
    double s, c;
    sincos(2.0 * 3.14159265358979323846 * (double)t / (double)NFFT, &s, &c);
    g_tw[t] = make_float2((float)c, (float)(-s));
}

// fwd_kernel: blocks [0, NPAIR*NBLK) do x spectra; blocks [NPAIR*NBLK, +NP) do IR partitions
__global__ void __launch_bounds__(NTH, 2) fwd_kernel(const float* __restrict__ x,
                                                     const float* __restrict__ ir) {
    extern __shared__ float2 sm[];
    const int b = blockIdx.x;
    const int tid = threadIdx.x;

    if (b < NPAIR * NBLK) {
        const int pair = b / NBLK;
        const int t = b - pair * NBLK;
        const float* x0 = x + (size_t)(2 * pair) * T;
        const float* x1 = x + (size_t)(2 * pair + 1) * T;
        const int off = (t - 1) * HOP;      // multiple of 4096 (possibly negative)
        #pragma unroll
        for (int i = 0; i < 4; i++) {
            int j = 4 * (tid + NTH * i);
            int n = off + j;
            float4 v0 = make_float4(0.f, 0.f, 0.f, 0.f), v1 = v0;
            if (n >= 0 && n < T) {          // vector-aligned: n%4==0, T%4==0
                v0 = *(const float4*)(x0 + n);
                v1 = *(const float4*)(x1 + n);
            }
            sm[SWZ(j + 0)] = make_float2(v0.x, v1.x);
            sm[SWZ(j + 1)] = make_float2(v0.y, v1.y);
            sm[SWZ(j + 2)] = make_float2(v0.z, v1.z);
            sm[SWZ(j + 3)] = make_float2(v0.w, v1.w);
        }
        __syncthreads();
        fft8192_ip(sm, 1.f);
        uint4* dst = (uint4*)(g_spec + (size_t)b * NFFT);
        #pragma unroll
        for (int i = 0; i < 4; i++) {
            int k4 = tid + NTH * i;
            int kb = 4 * k4;
            float2 v0 = sm[SWZ(kb + 0)], v1 = sm[SWZ(kb + 1)];
            float2 v2 = sm[SWZ(kb + 2)], v3 = sm[SWZ(kb + 3)];
            uint4 o;
            *(__half2*)&o.x = __floats2half2_rn(v0.x, v0.y);
            *(__half2*)&o.y = __floats2half2_rn(v1.x, v1.y);
            *(__half2*)&o.z = __floats2half2_rn(v2.x, v2.y);
            *(__half2*)&o.w = __floats2half2_rn(v3.x, v3.y);
            dst[k4] = o;
        }
    } else {
        const int p = b - NPAIR * NBLK;
        for (int j = tid; j < NFFT; j += NTH) {
            int idx = p * HOP + j;
            float v = (j < HOP && idx < L) ? ir[idx] : 0.f;
            sm[SWZ(j)] = make_float2(v, 0.f);
        }
        __syncthreads();
        fft8192_ip(sm, 1.f);
        const float inv = 1.f / (float)NFFT;
        float2* dst = g_H + (size_t)p * NFFT;
        for (int k = tid; k < NFFT; k += NTH) {
            float2 v = sm[SWZ(k)];
            dst[k] = make_float2(v.x * inv, v.y * inv);
        }
    }
}

// complex MAC: 4 half2 X complexes (uint4) times 4 fp32 H complexes (2 x float4)
DI void cmac4(float4& a01, float4& a23, const uint4& xv,
              const float4& h01, const float4& h23) {
    const __half2* xh = (const __half2*)&xv;
    float2 x0 = __half22float2(xh[0]);
    float2 x1 = __half22float2(xh[1]);
    float2 x2 = __half22float2(xh[2]);
    float2 x3 = __half22float2(xh[3]);
    a01.x += x0.x * h01.x - x0.y * h01.y;
    a01.y += x0.x * h01.y + x0.y * h01.x;
    a01.z += x1.x * h01.z - x1.y * h01.w;
    a01.w += x1.x * h01.w + x1.y * h01.z;
    a23.x += x2.x * h23.x - x2.y * h23.y;
    a23.y += x2.x * h23.y + x2.y * h23.x;
    a23.z += x3.x * h23.z - x3.y * h23.w;
    a23.w += x3.x * h23.w + x3.y * h23.z;
}

__global__ void __launch_bounds__(NTH, 2) out_kernel(const float* __restrict__ x,
                                                     const float* __restrict__ wetp,
                                                     float* __restrict__ out) {
    extern __shared__ float2 sm[];
    const int b = blockIdx.x;
    const int pair = b / NBLK;
    const int t = b - pair * NBLK;
    const int tid = threadIdx.x;

    // ---- accumulate acc[k] = sum_p X[t-p][k] * H[p][k] ----
    // i-outer: only 2 float4 accumulators live at a time; each quad's result
    // goes straight to (idle) smem. Ordered by the pre-IFFT __syncthreads.
    const uint4* Xbase = (const uint4*)(g_spec + (size_t)(pair * NBLK + t) * NFFT);

    #pragma unroll
    for (int i = 0; i < 4; i++) {
        const int f = tid + NTH * i;          // quad index: 4 complexes each
        float4 a01 = make_float4(0.f, 0.f, 0.f, 0.f);
        float4 a23 = make_float4(0.f, 0.f, 0.f, 0.f);
        if (t >= NP - 1) {
            #pragma unroll
            for (int p = 0; p < NP; p++) {
                const uint4* X4 = Xbase - (size_t)p * (NFFT / 4);
                const float4* H4 = (const float4*)(g_H + (size_t)p * NFFT);
                uint4 xv = X4[f];
                float4 h01 = H4[2 * f];
                float4 h23 = H4[2 * f + 1];
                cmac4(a01, a23, xv, h01, h23);
            }
        } else {
            for (int p = 0; p <= t; p++) {
                const uint4* X4 = Xbase - (size_t)p * (NFFT / 4);
                const float4* H4 = (const float4*)(g_H + (size_t)p * NFFT);
                uint4 xv = X4[f];
                float4 h01 = H4[2 * f];
                float4 h23 = H4[2 * f + 1];
                cmac4(a01, a23, xv, h01, h23);
            }
        }
        const int base = 4 * f;
        sm[SWZ(base + 0)] = make_float2(a01.x, a01.y);
        sm[SWZ(base + 1)] = make_float2(a01.z, a01.w);
        sm[SWZ(base + 2)] = make_float2(a23.x, a23.y);
        sm[SWZ(base + 3)] = make_float2(a23.z, a23.w);
    }
    __syncthreads();

    // ---- unnormalized inverse FFT (H prescaled by 1/N) ----
    fft8192_ip(sm, -1.f);

    // ---- fused wet/dry store: valid samples are second half j in [HOP, NFFT) ----
    const float wet = 1.f / (1.f + __expf(-wetp[0]));
    const float dry = 1.f - wet;
    const float* x0 = x + (size_t)(2 * pair) * T;
    const float* x1 = x + (size_t)(2 * pair + 1) * T;
    float* o0 = out + (size_t)(2 * pair) * T;
    float* o1 = out + (size_t)(2 * pair + 1) * T;
    #pragma unroll
    for (int i = 0; i < 2; i++) {
        int u = 4 * (tid + NTH * i);
        int n = t * HOP + u;
        if (n < T) {                         // n%4==0, T%4==0 -> whole vector valid
            float2 y0 = sm[SWZ(HOP + u + 0)];
            float2 y1 = sm[SWZ(HOP + u + 1)];
            float2 y2 = sm[SWZ(HOP + u + 2)];
            float2 y3 = sm[SWZ(HOP + u + 3)];
            float4 v0 = *(const float4*)(x0 + n);
            float4 v1 = *(const float4*)(x1 + n);
            float4 r0 = make_float4(dry * v0.x + wet * y0.x, dry * v0.y + wet * y1.x,
                                    dry * v0.z + wet * y2.x, dry * v0.w + wet * y3.x);
            float4 r1 = make_float4(dry * v1.x + wet * y0.y, dry * v1.y + wet * y1.y,
                                    dry * v1.z + wet * y2.y, dry * v1.w + wet * y3.y);
            *(float4*)(o0 + n) = r0;
            *(float4*)(o1 + n) = r1;
        }
    }
}

// ---------------- launch ----------------
extern "C" void kernel_launch(void* const* d_in, const int* in_sizes, int n_in,
                              void* d_out, int out_size) {
    const float* x    = (const float*)d_in[0];
    const float* ir   = (const float*)d_in[1];
    const float* wetp = (const float*)d_in[2];
    float* out        = (float*)d_out;

    cudaFuncSetAttribute(fwd_kernel, cudaFuncAttributeMaxDynamicSharedMemorySize, SMEMB);
    cudaFuncSetAttribute(out_kernel, cudaFuncAttributeMaxDynamicSharedMemorySize, SMEMB);

    twiddle_kernel<<<NFFT / 256, 256>>>();
    fwd_kernel<<<NPAIR * NBLK + NP, NTH, SMEMB>>>(x, ir);
    out_kernel<<<NPAIR * NBLK, NTH, SMEMB>>>(x, wetp, out);
}